// round 16
// baseline (speedup 1.0000x reference)
#include <cuda_runtime.h>
#include <cuda_bf16.h>

// Problem constants (fixed by setup_inputs)
#define B_ 64
#define N_ 1024
#define E_ 16384
#define D_ 1024
#define C_ 128

#define NB 148          // 1 block per SM (B300:148, GB300:152) -> co-resident
#define NT 1024
#define FULLM 0xffffffffu
#define DMAXP1 (E_ + 1) // degree value range bound
#define VW 192          // rank-count matrix width (nd <= 181 by pigeonhole)

// ---------------- device scratch (static, no allocations) ----------------
// deg/flag2/flag3/flagd/nd/V are cleared at the END of each launch (zero-init at load).
__device__ __align__(16) int g_src[E_];
__device__ __align__(16) int g_dst[E_];
__device__ int   g_deg[N_];
__device__ int   g_nrank[N_];           // node -> degree-rank
__device__ int   g_rowptr[N_ + 1];
__device__ int   g_cursor[N_];          // atomic fill cursors (= rowptr at P2 start)
__device__ int   g_col[E_];
__device__ int   g_V[N_ * VW];          // per-node neighbor-rank counts (frontier2)
__device__ int   g_flag2[N_], g_flag3[N_];
__device__ int   g_list2[N_], g_list3[N_];
__device__ int   g_c2, g_c3;
__device__ int   g_flagd[DMAXP1];       // degree-value claimed flags
__device__ int   g_degrank[DMAXP1];     // degree value -> rank
__device__ float g_dval[N_];            // rank -> degree value (as float)
__device__ int   g_nd;                  // number of distinct degree values
__device__ __align__(16) float g_w0[B_ * C_];      // (h0 @ W_conv) per batch
__device__ __align__(16) float g_G[N_ * B_ * C_];  // G[rank][b][c]
__device__ __align__(16) float g_H2[B_ * N_ * C_]; // node-indexed (frontier2 rows)
__device__ __align__(16) float g_H3[B_ * N_ * C_]; // node-indexed (frontier3 rows)

// ---------------- software grid barrier (all blocks resident) ----------------
__device__ volatile unsigned g_gen;
__device__ unsigned          g_count;

__device__ __forceinline__ void gsync(unsigned gen0, unsigned k) {
    __syncthreads();
    if (threadIdx.x == 0) {
        __threadfence();
        if (atomicAdd(&g_count, 1u) == NB - 1u) {
            g_count = 0u;
            __threadfence();
            g_gen = gen0 + k;
        } else {
            while (g_gen != gen0 + k) { __nanosleep(32); }
        }
        __threadfence();
    }
    __syncthreads();
}

// ---------------- f32x2 packed helpers (Blackwell) ---------------------------
__device__ __forceinline__ void ffma2(unsigned long long& d,
                                      unsigned long long a, unsigned long long b) {
    asm("fma.rn.f32x2 %0, %1, %2, %0;" : "+l"(d) : "l"(a), "l"(b));
}
__device__ __forceinline__ unsigned long long pack2(float lo, float hi) {
    unsigned long long r;
    asm("mov.b64 %0, {%1, %2};" : "=l"(r) : "f"(lo), "f"(hi));
    return r;
}
__device__ __forceinline__ float unpack_sum(unsigned long long v) {
    float lo, hi;
    asm("mov.b64 {%0, %1}, %2;" : "=f"(lo), "=f"(hi) : "l"(v));
    return lo + hi;
}

// inclusive scan across 1024 threads: shfl warp scan + warp-sum scan (2 barriers)
__device__ __forceinline__ int scan1(int v, int t, int* s) {
    int lane = t & 31, w = t >> 5;               // 32 warps
    int inc = v;
#pragma unroll
    for (int off = 1; off < 32; off <<= 1) {
        int u = __shfl_up_sync(FULLM, inc, off);
        if (lane >= off) inc += u;
    }
    if (lane == 31) s[w] = inc;
    __syncthreads();
    if (w == 0) {
        int x = s[lane];
#pragma unroll
        for (int off = 1; off < 32; off <<= 1) {
            int u = __shfl_up_sync(FULLM, x, off);
            if (lane >= off) x += u;
        }
        s[lane] = x;
    }
    __syncthreads();
    return inc + (w ? s[w - 1] : 0);
}

__device__ __forceinline__ void compact_flags(const int* flags, int* list, int* cnt_out,
                                              int t, int* s) {
    int f = flags[t];
    int incl = scan1(f, t, s);
    if (f) list[incl - 1] = t;
    if (t == NT - 1) *cnt_out = incl;
}

__global__ __launch_bounds__(NT) void k_mega(
    const float* __restrict__ x, const void* __restrict__ eidx,
    const float* __restrict__ W_emb,  const float* __restrict__ b_emb,
    const float* __restrict__ W_conv, const float* __restrict__ b_conv,
    const float* __restrict__ W_cls,  const float* __restrict__ b_cls,
    float* __restrict__ out)
{
    __shared__ __align__(16) float sm[8192];     // 32 KB, unioned across phases
    const int t   = threadIdx.x;
    const int bid = blockIdx.x;
    const unsigned gen0 = g_gen;

    // ======== P0: embedding + w0 (blocks 0..63, ONE batch each, float4 W_emb)
    //          || edge convert + deg + flag3 (blocks 64..79)
    if (bid < 64) {
        int b = bid;
        float* xs   = sm;             // [1024]
        float* part = sm + 1024;      // [32][128]
        float* h0   = sm + 5120;      // [128]
        xs[t] = x[b * D_ + t];
        __syncthreads();
        int c4 = (t & 31) * 4, ds = t >> 5;       // 32 c-quads x 32 d-slices
        int d0 = ds * 32;
        float4 A = {0.f, 0.f, 0.f, 0.f};
#pragma unroll 4
        for (int d = d0; d < d0 + 32; d++) {
            float4 w = *(const float4*)&W_emb[d * C_ + c4];   // coalesced 512B/warp
            float x0 = xs[d];
            A.x += x0 * w.x; A.y += x0 * w.y; A.z += x0 * w.z; A.w += x0 * w.w;
        }
        *(float4*)&part[ds * 128 + c4] = A;
        __syncthreads();
        int c = t & 127, g8 = t >> 7;
        float a = part[(g8 * 4 + 0) * 128 + c] + part[(g8 * 4 + 1) * 128 + c]
                + part[(g8 * 4 + 2) * 128 + c] + part[(g8 * 4 + 3) * 128 + c];
        __syncthreads();
        part[g8 * 128 + c] = a;                   // reuse rows 0..7
        __syncthreads();
        if (t < 128) {
            float h = b_emb[t];
#pragma unroll
            for (int s = 0; s < 8; s++) h += part[s * 128 + t];
            h0[t] = fmaxf(h, 0.f);
        }
        __syncthreads();
        // w0[b] = h0 @ W_conv, 8 k-slices of 16, coalesced scalar W_conv loads
        int ks = g8, k0 = ks * 16;
        float p = 0.f;
#pragma unroll
        for (int k = k0; k < k0 + 16; k++)
            p += h0[k] * W_conv[k * C_ + c];      // coalesced 128B/warp
        __syncthreads();
        part[ks * 128 + c] = p;
        __syncthreads();
        if (t < 128) {
            float a2 = 0.f;
#pragma unroll
            for (int s = 0; s < 8; s++) a2 += part[s * 128 + t];
            g_w0[b * C_ + t] = a2;
        }
    } else if (bid < 80) {
        int e = (bid - 64) * 1024 + t;            // 16*1024 == E_
        const unsigned* ew32 = (const unsigned*)eidx;
        int any = __syncthreads_or(ew32[2 * e + 1] != 0u);
        int is64 = !any;                          // int64 => high words all zero
        int s, d;
        if (is64) {
            const long long* p = (const long long*)eidx;
            s = (int)p[e]; d = (int)p[E_ + e];
        } else {
            const int* p = (const int*)eidx;
            s = p[e]; d = p[E_ + e];
        }
        g_src[e] = s; g_dst[e] = d;
        atomicAdd(&g_deg[d], 1);
        if (d == 0) g_flag3[s] = 1;
    }
    gsync(gen0, 1);

    // ======== P1: flag2 (0..15) || rowptr+cursor scan (16) || flag3 compact (17)
    //          || degree-rank claim + node-rank (18)
    if (bid < 16) {
        int e = bid * 1024 + t;
        if (g_flag3[g_dst[e]]) g_flag2[g_src[e]] = 1;
    } else if (bid == 16) {
        int d = g_deg[t];
        int incl = scan1(d, t, (int*)sm);
        g_rowptr[t + 1] = incl;
        g_cursor[t] = incl - d;                   // exclusive prefix = rowptr[t]
        if (t == 0) g_rowptr[0] = 0;
    } else if (bid == 17) {
        compact_flags(g_flag3, g_list3, &g_c3, t, (int*)sm);
    } else if (bid == 18) {
        int d = g_deg[t];                          // thread t handles node t
        int old = atomicExch(&g_flagd[d], 1);
        if (old == 0) {
            int r = atomicAdd(&g_nd, 1);
            g_degrank[d] = r;
            g_dval[r] = (float)d;
        }
        __syncthreads();
        g_nrank[t] = g_degrank[d];
    }
    gsync(gen0, 2);

    // ======== P2: csrfill + V-count build (blocks 0..15, edge-parallel)
    //          || G-table build, 4-way split (16..146) || flag2 compact (147)
    if (bid < 16) {
        int e = bid * 1024 + t;
        int d = g_dst[e], s = g_src[e];
        int pos = atomicAdd(&g_cursor[d], 1);
        g_col[pos] = s;
        if (g_flag2[d]) atomicAdd(&g_V[d * VW + g_nrank[s]], 1);
    } else if (bid < 147) {
        // item = (rank, 16-row quarter); per thread: 2 rows of the quarter
        int nd4 = g_nd * 4;
        int c = t & 127, rg = t >> 7;             // 8 groups x 2 local rows
        float bc = b_conv[c];
        float (*As)[C_] = (float (*)[C_])sm;      // [16][128]
        for (int item = bid - 16; item < nd4; item += 131) {
            int rank = item >> 2, r0 = (item & 3) * 16;
            float dv = g_dval[rank];
            int lr = rg * 2;                      // local rows lr, lr+1
            As[lr + 0][c] = fmaxf(dv * g_w0[(r0 + lr + 0) * C_ + c] + bc, 0.f);
            As[lr + 1][c] = fmaxf(dv * g_w0[(r0 + lr + 1) * C_ + c] + bc, 0.f);
            __syncthreads();
            unsigned long long a0 = 0ull, a1 = 0ull;
#pragma unroll 4
            for (int k = 0; k < C_; k += 4) {
                unsigned long long w01 = pack2(W_conv[(k + 0) * C_ + c],
                                               W_conv[(k + 1) * C_ + c]);
                unsigned long long w23 = pack2(W_conv[(k + 2) * C_ + c],
                                               W_conv[(k + 3) * C_ + c]);
                const ulonglong2 av0 = *(const ulonglong2*)&As[lr + 0][k];
                const ulonglong2 av1 = *(const ulonglong2*)&As[lr + 1][k];
                ffma2(a0, av0.x, w01); ffma2(a0, av0.y, w23);
                ffma2(a1, av1.x, w01); ffma2(a1, av1.y, w23);
            }
            g_G[(rank * B_ + r0 + lr + 0) * C_ + c] = unpack_sum(a0);
            g_G[(rank * B_ + r0 + lr + 1) * C_ + c] = unpack_sum(a1);
            __syncthreads();
        }
    } else {
        compact_flags(g_flag2, g_list2, &g_c2, t, (int*)sm);
    }
    gsync(gen0, 3);

    // ======== P3: conv2 as dense rank-space GEMM: H2 = relu(V x G + bc) ======
    // tile = 16 nodes x 1024 (b,c)-columns; V tile in smem, G streamed coalesced
    {
        int cnt2 = g_c2, nd = g_nd;
        int nrt = (cnt2 + 15) >> 4;
        int ntiles = nrt * 8;                     // 8 column tiles of 1024
        float* sV   = sm;                         // [nd][16] (<= 3072 floats)
        int*  sList = (int*)(sm + 3072);          // [16]
        for (int tile = bid; tile < ntiles; tile += NB) {
            int rt = tile >> 3, ct = tile & 7;
            int row0 = rt * 16;
            int col = ct * 1024 + t;
            if (t < 16) {
                int idx = row0 + t;
                sList[t] = (idx < cnt2) ? g_list2[idx] : -1;
            }
            __syncthreads();
            for (int idx = t; idx < nd * 16; idx += NT) {
                int i = idx & 15, r = idx >> 4;
                int n = sList[i];
                sV[r * 16 + i] = (n >= 0) ? (float)g_V[n * VW + r] : 0.f;
            }
            __syncthreads();
            int b = col >> 7, c = col & 127;
            float bc = b_conv[c];
            float acc[16];
#pragma unroll
            for (int i = 0; i < 16; i++) acc[i] = 0.f;
            for (int r = 0; r < nd; r++) {
                float g = g_G[r * (B_ * C_) + col];          // coalesced 128B/warp
                float4 v0 = *(const float4*)&sV[r * 16 + 0]; // LDS.128 broadcast
                float4 v1 = *(const float4*)&sV[r * 16 + 4];
                float4 v2 = *(const float4*)&sV[r * 16 + 8];
                float4 v3 = *(const float4*)&sV[r * 16 + 12];
                acc[0]  += v0.x * g; acc[1]  += v0.y * g;
                acc[2]  += v0.z * g; acc[3]  += v0.w * g;
                acc[4]  += v1.x * g; acc[5]  += v1.y * g;
                acc[6]  += v1.z * g; acc[7]  += v1.w * g;
                acc[8]  += v2.x * g; acc[9]  += v2.y * g;
                acc[10] += v2.z * g; acc[11] += v2.w * g;
                acc[12] += v3.x * g; acc[13] += v3.y * g;
                acc[14] += v3.z * g; acc[15] += v3.w * g;
            }
#pragma unroll
            for (int i = 0; i < 16; i++) {
                int n = sList[i];
                if (n >= 0)
                    g_H2[(b * N_ + n) * C_ + c] = fmaxf(acc[i] + bc, 0.f);
            }
            __syncthreads();
        }
    }
    gsync(gen0, 4);

    // ======== P4: conv3 fused agg + f32x2 GEMM + relu (one 8-row tile/block) ==
    {
        int cnt3 = g_c3;
        int M3 = B_ * cnt3;
        int ntiles = (M3 + 7) >> 3;
        int grp = t >> 7, c = t & 127;
        float bc = b_conv[c];
        float (*As)[C_] = (float (*)[C_])sm;      // [8][128], group grp owns row grp
        for (int tile = bid; tile < ntiles; tile += NB) {
            int rr = tile * 8 + grp;
            int b = 0, i = 0;
            float acc = 0.f;
            if (rr < M3) {
                b = rr / cnt3; i = rr - b * cnt3;
                int n = g_list3[i];
                int s0 = g_rowptr[n], s1 = g_rowptr[n + 1];
#pragma unroll 8
                for (int q = s0; q < s1; q++)
                    acc += g_H2[(b * N_ + g_col[q]) * C_ + c];
            }
            As[grp][c] = acc;
            __syncthreads();
            unsigned long long acc2 = 0ull;
#pragma unroll 4
            for (int k = 0; k < C_; k += 4) {
                unsigned long long w01 = pack2(W_conv[(k + 0) * C_ + c],
                                               W_conv[(k + 1) * C_ + c]);
                unsigned long long w23 = pack2(W_conv[(k + 2) * C_ + c],
                                               W_conv[(k + 3) * C_ + c]);
                const ulonglong2 av = *(const ulonglong2*)&As[grp][k];
                ffma2(acc2, av.x, w01);
                ffma2(acc2, av.y, w23);
            }
            if (rr < M3)
                g_H3[(b * N_ + g_list3[i]) * C_ + c] =
                    fmaxf(unpack_sum(acc2) + bc, 0.f);
            __syncthreads();
        }
    }
    gsync(gen0, 5);

    // ======== P5: conv4 agg (node 0) + GEMM + classifier (blocks 0..63)
    //          || clear scratch for next launch (blocks 64..147)
    if (bid < B_) {
        float* part = sm;            // [8][128]
        float* s4   = sm + 1024;     // [128]
        float* red  = sm + 1152;     // [128]
        int ks = t >> 7, c = t & 127;
        int s0 = g_rowptr[0], s1 = g_rowptr[1];
        float acc = 0.f;
        for (int q = s0 + ks; q < s1; q += 8)
            acc += g_H3[(bid * N_ + g_col[q]) * C_ + c];
        part[ks * 128 + c] = acc;
        __syncthreads();
        if (t < 128) {
            float a = 0.f;
#pragma unroll
            for (int s = 0; s < 8; s++) a += part[s * 128 + t];
            s4[t] = a;
        }
        __syncthreads();
        int k0 = ks * 16;
        float p = 0.f;
#pragma unroll
        for (int k = k0; k < k0 + 16; k++) p += s4[k] * W_conv[k * C_ + c];
        __syncthreads();
        part[ks * 128 + c] = p;
        __syncthreads();
        if (t < 128) {
            float a2 = b_conv[t];
#pragma unroll
            for (int s = 0; s < 8; s++) a2 += part[s * 128 + t];
            red[t] = fmaxf(a2, 0.f) * W_cls[t];
        }
        __syncthreads();
#pragma unroll
        for (int off = 64; off > 0; off >>= 1) {
            if (t < off) red[t] += red[t + off];
            __syncthreads();
        }
        if (t == 0) out[bid] = red[0] + b_cls[0];
    } else if (bid == 64) {
        g_deg[t] = 0;
    } else if (bid == 65) {
        g_flag2[t] = 0;
    } else if (bid == 66) {
        g_flag3[t] = 0;
    } else if (bid == 67) {
        int nd = g_nd;
        if (t < nd) g_flagd[(int)g_dval[t]] = 0;
        __syncthreads();
        if (t == 0) g_nd = 0;
    } else {
        // clear V count matrix (blocks 68..147): N_*VW ints
        for (int idx = (bid - 68) * NT + t; idx < N_ * VW; idx += 80 * NT)
            g_V[idx] = 0;
    }
}

extern "C" void kernel_launch(void* const* d_in, const int* in_sizes, int n_in,
                              void* d_out, int out_size) {
    (void)in_sizes; (void)n_in; (void)out_size;
    const float* x      = (const float*)d_in[0];
    const void*  eidx   = d_in[1];
    const float* W_emb  = (const float*)d_in[2];
    const float* b_emb  = (const float*)d_in[3];
    const float* W_conv = (const float*)d_in[4];
    const float* b_conv = (const float*)d_in[5];
    const float* W_cls  = (const float*)d_in[6];
    const float* b_cls  = (const float*)d_in[7];
    float* out = (float*)d_out;

    k_mega<<<NB, NT>>>(x, eidx, W_emb, b_emb, W_conv, b_conv, W_cls, b_cls, out);
}

// round 17
// speedup vs baseline: 1.0712x; 1.0712x over previous
#include <cuda_runtime.h>
#include <cuda_bf16.h>

// Problem constants (fixed by setup_inputs)
#define B_ 64
#define N_ 1024
#define E_ 16384
#define D_ 1024
#define C_ 128

#define NB 148          // 1 block per SM (B300:148, GB300:152) -> co-resident
#define NT 1024
#define FULLM 0xffffffffu
#define DMAXP1 (E_ + 1) // degree value range bound
#define VW 192          // rank-count matrix width (nd <= 181 by pigeonhole)

// ---------------- device scratch (static, no allocations) ----------------
// deg/flag2/flag3/flagd/nd/V/counters cleared at END of each launch (zero-init at load).
__device__ __align__(16) int g_src[E_];
__device__ __align__(16) int g_dst[E_];
__device__ int   g_deg[N_];
__device__ int   g_nrank[N_];           // node -> degree-rank
__device__ int   g_rowptr[N_ + 1];
__device__ int   g_cursor[N_];          // atomic fill cursors (= rowptr at csrfill start)
__device__ int   g_col[E_];
__device__ int   g_V[N_ * VW];          // per-node neighbor-rank counts (frontier2)
__device__ int   g_flag2[N_], g_flag3[N_];
__device__ int   g_list2[N_], g_list3[N_];
__device__ int   g_c2, g_c3;
__device__ int   g_flagd[DMAXP1];       // degree-value claimed flags
__device__ int   g_degrank[DMAXP1];     // degree value -> rank
__device__ float g_dval[N_];            // rank -> degree value (as float)
__device__ int   g_nd;                  // number of distinct degree values
__device__ __align__(16) float g_w0[B_ * C_];      // (h0 @ W_conv) per batch
__device__ __align__(16) float g_G[N_ * B_ * C_];  // G[rank][b][c]
__device__ __align__(16) float g_H2[B_ * N_ * C_]; // node-indexed (frontier2 rows)
__device__ __align__(16) float g_H3[B_ * N_ * C_]; // node-indexed (frontier3 rows)

// ---------------- DAG counters + software grid barrier -----------------------
// g_cnt[0]=convert(16) [1]=scan(1) [2]=rank(1) [3]=flag2(16) [4]=emb(64)
__device__ int g_cnt[8];
__device__ volatile unsigned g_gen;
__device__ unsigned          g_count;

__device__ __forceinline__ void block_arrive(int idx) {
    __syncthreads();
    if (threadIdx.x == 0) { __threadfence(); atomicAdd(&g_cnt[idx], 1); }
}
__device__ __forceinline__ void block_wait(int idx, int target) {
    if (threadIdx.x == 0) {
        while (((volatile int*)g_cnt)[idx] < target) { __nanosleep(32); }
        __threadfence();
    }
    __syncthreads();
}

__device__ __forceinline__ void gsync(unsigned gen0, unsigned k) {
    __syncthreads();
    if (threadIdx.x == 0) {
        __threadfence();
        if (atomicAdd(&g_count, 1u) == NB - 1u) {
            g_count = 0u;
            __threadfence();
            g_gen = gen0 + k;
        } else {
            while (g_gen != gen0 + k) { __nanosleep(32); }
        }
        __threadfence();
    }
    __syncthreads();
}

// ---------------- f32x2 packed helpers (Blackwell) ---------------------------
__device__ __forceinline__ void ffma2(unsigned long long& d,
                                      unsigned long long a, unsigned long long b) {
    asm("fma.rn.f32x2 %0, %1, %2, %0;" : "+l"(d) : "l"(a), "l"(b));
}
__device__ __forceinline__ unsigned long long pack2(float lo, float hi) {
    unsigned long long r;
    asm("mov.b64 %0, {%1, %2};" : "=l"(r) : "f"(lo), "f"(hi));
    return r;
}
__device__ __forceinline__ float unpack_sum(unsigned long long v) {
    float lo, hi;
    asm("mov.b64 {%0, %1}, %2;" : "=f"(lo), "=f"(hi) : "l"(v));
    return lo + hi;
}

// inclusive scan across 1024 threads: shfl warp scan + warp-sum scan (2 barriers)
__device__ __forceinline__ int scan1(int v, int t, int* s) {
    int lane = t & 31, w = t >> 5;               // 32 warps
    int inc = v;
#pragma unroll
    for (int off = 1; off < 32; off <<= 1) {
        int u = __shfl_up_sync(FULLM, inc, off);
        if (lane >= off) inc += u;
    }
    if (lane == 31) s[w] = inc;
    __syncthreads();
    if (w == 0) {
        int x = s[lane];
#pragma unroll
        for (int off = 1; off < 32; off <<= 1) {
            int u = __shfl_up_sync(FULLM, x, off);
            if (lane >= off) x += u;
        }
        s[lane] = x;
    }
    __syncthreads();
    return inc + (w ? s[w - 1] : 0);
}

__device__ __forceinline__ void compact_flags(const int* flags, int* list, int* cnt_out,
                                              int t, int* s) {
    int f = flags[t];
    int incl = scan1(f, t, s);
    if (f) list[incl - 1] = t;
    if (t == NT - 1) *cnt_out = incl;
}

// G-table build: worker widx of 128, items = (rank, 16-row quarter)
__device__ __forceinline__ void g_build(int widx, int t, float* sm,
                                        const float* __restrict__ W_conv,
                                        const float* __restrict__ b_conv) {
    int nd4 = g_nd * 4;
    int c = t & 127, rg = t >> 7;                 // 8 groups x 2 local rows
    float bc = b_conv[c];
    float (*As)[C_] = (float (*)[C_])sm;          // [16][128]
    for (int item = widx; item < nd4; item += 128) {
        int rank = item >> 2, r0 = (item & 3) * 16;
        float dv = g_dval[rank];
        int lr = rg * 2;                          // local rows lr, lr+1
        As[lr + 0][c] = fmaxf(dv * g_w0[(r0 + lr + 0) * C_ + c] + bc, 0.f);
        As[lr + 1][c] = fmaxf(dv * g_w0[(r0 + lr + 1) * C_ + c] + bc, 0.f);
        __syncthreads();
        unsigned long long a0 = 0ull, a1 = 0ull;
#pragma unroll 4
        for (int k = 0; k < C_; k += 4) {
            unsigned long long w01 = pack2(W_conv[(k + 0) * C_ + c],
                                           W_conv[(k + 1) * C_ + c]);
            unsigned long long w23 = pack2(W_conv[(k + 2) * C_ + c],
                                           W_conv[(k + 3) * C_ + c]);
            const ulonglong2 av0 = *(const ulonglong2*)&As[lr + 0][k];
            const ulonglong2 av1 = *(const ulonglong2*)&As[lr + 1][k];
            ffma2(a0, av0.x, w01); ffma2(a0, av0.y, w23);
            ffma2(a1, av1.x, w01); ffma2(a1, av1.y, w23);
        }
        g_G[(rank * B_ + r0 + lr + 0) * C_ + c] = unpack_sum(a0);
        g_G[(rank * B_ + r0 + lr + 1) * C_ + c] = unpack_sum(a1);
        __syncthreads();
    }
}

__global__ __launch_bounds__(NT) void k_mega(
    const float* __restrict__ x, const void* __restrict__ eidx,
    const float* __restrict__ W_emb,  const float* __restrict__ b_emb,
    const float* __restrict__ W_conv, const float* __restrict__ b_conv,
    const float* __restrict__ W_cls,  const float* __restrict__ b_cls,
    float* __restrict__ out)
{
    __shared__ __align__(16) float sm[8192];     // 32 KB, unioned across phases
    const int t   = threadIdx.x;
    const int bid = blockIdx.x;
    const unsigned gen0 = g_gen;

    // ======== Front region: DAG-scheduled producers (no global barrier) ======
    if (bid < 64) {
        // ---- embedding + w0 (one batch), then join G-build workers 0..63 ----
        int b = bid;
        float* xs   = sm;             // [1024]
        float* part = sm + 1024;      // [32][128]
        float* h0   = sm + 5120;      // [128]
        xs[t] = x[b * D_ + t];
        __syncthreads();
        int c4 = (t & 31) * 4, ds = t >> 5;       // 32 c-quads x 32 d-slices
        int d0 = ds * 32;
        float4 A = {0.f, 0.f, 0.f, 0.f};
#pragma unroll 4
        for (int d = d0; d < d0 + 32; d++) {
            float4 w = *(const float4*)&W_emb[d * C_ + c4];   // coalesced 512B/warp
            float x0 = xs[d];
            A.x += x0 * w.x; A.y += x0 * w.y; A.z += x0 * w.z; A.w += x0 * w.w;
        }
        *(float4*)&part[ds * 128 + c4] = A;
        __syncthreads();
        int c = t & 127, g8 = t >> 7;
        float a = part[(g8 * 4 + 0) * 128 + c] + part[(g8 * 4 + 1) * 128 + c]
                + part[(g8 * 4 + 2) * 128 + c] + part[(g8 * 4 + 3) * 128 + c];
        __syncthreads();
        part[g8 * 128 + c] = a;                   // reuse rows 0..7
        __syncthreads();
        if (t < 128) {
            float h = b_emb[t];
#pragma unroll
            for (int s = 0; s < 8; s++) h += part[s * 128 + t];
            h0[t] = fmaxf(h, 0.f);
        }
        __syncthreads();
        int ks = g8, k0 = ks * 16;
        float p = 0.f;
#pragma unroll
        for (int k = k0; k < k0 + 16; k++)
            p += h0[k] * W_conv[k * C_ + c];      // coalesced 128B/warp
        __syncthreads();
        part[ks * 128 + c] = p;
        __syncthreads();
        if (t < 128) {
            float a2 = 0.f;
#pragma unroll
            for (int s = 0; s < 8; s++) a2 += part[s * 128 + t];
            g_w0[b * C_ + t] = a2;
        }
        block_arrive(4);                          // emb done
        block_wait(4, 64);
        block_wait(2, 1);                         // rank ready
        g_build(bid, t, sm, W_conv, b_conv);
    } else if (bid < 80) {
        // ---- edge convert + deg + flag3, then csrfill + V ----
        int e = (bid - 64) * 1024 + t;            // 16*1024 == E_
        const unsigned* ew32 = (const unsigned*)eidx;
        int any = __syncthreads_or(ew32[2 * e + 1] != 0u);
        int is64 = !any;                          // int64 => high words all zero
        int s, d;
        if (is64) {
            const long long* p = (const long long*)eidx;
            s = (int)p[e]; d = (int)p[E_ + e];
        } else {
            const int* p = (const int*)eidx;
            s = p[e]; d = p[E_ + e];
        }
        g_src[e] = s; g_dst[e] = d;
        atomicAdd(&g_deg[d], 1);
        if (d == 0) g_flag3[s] = 1;
        block_arrive(0);                          // convert done
        block_wait(1, 1);                         // cursor/rowptr ready
        block_wait(2, 1);                         // nrank ready
        block_wait(3, 16);                        // flag2 ready (for V gating)
        int pos = atomicAdd(&g_cursor[d], 1);
        g_col[pos] = s;
        if (g_flag2[d]) atomicAdd(&g_V[d * VW + g_nrank[s]], 1);
    } else if (bid < 96) {
        // ---- flag2 (16 blocks), then join G-build workers 64..79 ----
        block_wait(0, 16);
        int e = (bid - 80) * 1024 + t;
        if (g_flag3[g_dst[e]]) g_flag2[g_src[e]] = 1;
        block_arrive(3);
        block_wait(4, 64);
        block_wait(2, 1);
        g_build(64 + (bid - 80), t, sm, W_conv, b_conv);
    } else if (bid == 96) {
        // ---- rowptr + cursor scan ----
        block_wait(0, 16);
        int d = g_deg[t];
        int incl = scan1(d, t, (int*)sm);
        g_rowptr[t + 1] = incl;
        g_cursor[t] = incl - d;                   // exclusive prefix = rowptr[t]
        if (t == 0) g_rowptr[0] = 0;
        block_arrive(1);
    } else if (bid == 97) {
        // ---- flag3 compaction ----
        block_wait(0, 16);
        compact_flags(g_flag3, g_list3, &g_c3, t, (int*)sm);
    } else if (bid == 98) {
        // ---- degree-rank claim + node-rank ----
        block_wait(0, 16);
        int d = g_deg[t];                          // thread t handles node t
        int old = atomicExch(&g_flagd[d], 1);
        if (old == 0) {
            int r = atomicAdd(&g_nd, 1);
            g_degrank[d] = r;
            g_dval[r] = (float)d;
        }
        __syncthreads();
        g_nrank[t] = g_degrank[d];
        block_arrive(2);
    } else if (bid == 99) {
        // ---- flag2 compaction ----
        block_wait(3, 16);
        compact_flags(g_flag2, g_list2, &g_c2, t, (int*)sm);
    } else {
        // ---- G-build workers 80..127 (blocks 100..147) ----
        block_wait(4, 64);
        block_wait(2, 1);
        g_build(80 + (bid - 100), t, sm, W_conv, b_conv);
    }
    gsync(gen0, 1);

    // ======== P3: conv2 as dense rank-space GEMM: H2 = relu(V x G + bc) ======
    {
        int cnt2 = g_c2, nd = g_nd;
        int nrt = (cnt2 + 15) >> 4;
        int ntiles = nrt * 8;                     // 8 column tiles of 1024
        float* sV   = sm;                         // [nd][16] (<= 3072 floats)
        int*  sList = (int*)(sm + 3072);          // [16]
        for (int tile = bid; tile < ntiles; tile += NB) {
            int rt = tile >> 3, ct = tile & 7;
            int row0 = rt * 16;
            int col = ct * 1024 + t;
            if (t < 16) {
                int idx = row0 + t;
                sList[t] = (idx < cnt2) ? g_list2[idx] : -1;
            }
            __syncthreads();
            for (int idx = t; idx < nd * 16; idx += NT) {
                int i = idx & 15, r = idx >> 4;
                int n = sList[i];
                sV[r * 16 + i] = (n >= 0) ? (float)g_V[n * VW + r] : 0.f;
            }
            __syncthreads();
            int b = col >> 7, c = col & 127;
            float bc = b_conv[c];
            float acc[16];
#pragma unroll
            for (int i = 0; i < 16; i++) acc[i] = 0.f;
            for (int r = 0; r < nd; r++) {
                float g = g_G[r * (B_ * C_) + col];          // coalesced 128B/warp
                float4 v0 = *(const float4*)&sV[r * 16 + 0]; // LDS.128 broadcast
                float4 v1 = *(const float4*)&sV[r * 16 + 4];
                float4 v2 = *(const float4*)&sV[r * 16 + 8];
                float4 v3 = *(const float4*)&sV[r * 16 + 12];
                acc[0]  += v0.x * g; acc[1]  += v0.y * g;
                acc[2]  += v0.z * g; acc[3]  += v0.w * g;
                acc[4]  += v1.x * g; acc[5]  += v1.y * g;
                acc[6]  += v1.z * g; acc[7]  += v1.w * g;
                acc[8]  += v2.x * g; acc[9]  += v2.y * g;
                acc[10] += v2.z * g; acc[11] += v2.w * g;
                acc[12] += v3.x * g; acc[13] += v3.y * g;
                acc[14] += v3.z * g; acc[15] += v3.w * g;
            }
#pragma unroll
            for (int i = 0; i < 16; i++) {
                int n = sList[i];
                if (n >= 0)
                    g_H2[(b * N_ + n) * C_ + c] = fmaxf(acc[i] + bc, 0.f);
            }
            __syncthreads();
        }
    }
    gsync(gen0, 2);

    // ======== P4: conv3 fused agg + f32x2 GEMM + relu (one 8-row tile/block) ==
    {
        int cnt3 = g_c3;
        int M3 = B_ * cnt3;
        int ntiles = (M3 + 7) >> 3;
        int grp = t >> 7, c = t & 127;
        float bc = b_conv[c];
        float (*As)[C_] = (float (*)[C_])sm;      // [8][128], group grp owns row grp
        for (int tile = bid; tile < ntiles; tile += NB) {
            int rr = tile * 8 + grp;
            int b = 0, i = 0;
            float acc = 0.f;
            if (rr < M3) {
                b = rr / cnt3; i = rr - b * cnt3;
                int n = g_list3[i];
                int s0 = g_rowptr[n], s1 = g_rowptr[n + 1];
#pragma unroll 8
                for (int q = s0; q < s1; q++)
                    acc += g_H2[(b * N_ + g_col[q]) * C_ + c];
            }
            As[grp][c] = acc;
            __syncthreads();
            unsigned long long acc2 = 0ull;
#pragma unroll 4
            for (int k = 0; k < C_; k += 4) {
                unsigned long long w01 = pack2(W_conv[(k + 0) * C_ + c],
                                               W_conv[(k + 1) * C_ + c]);
                unsigned long long w23 = pack2(W_conv[(k + 2) * C_ + c],
                                               W_conv[(k + 3) * C_ + c]);
                const ulonglong2 av = *(const ulonglong2*)&As[grp][k];
                ffma2(acc2, av.x, w01);
                ffma2(acc2, av.y, w23);
            }
            if (rr < M3)
                g_H3[(b * N_ + g_list3[i]) * C_ + c] =
                    fmaxf(unpack_sum(acc2) + bc, 0.f);
            __syncthreads();
        }
    }
    gsync(gen0, 3);

    // ======== P5: conv4 agg (node 0) + GEMM + classifier (blocks 0..63)
    //          || clear scratch for next launch (blocks 64..147)
    if (bid < B_) {
        float* part = sm;            // [8][128]
        float* s4   = sm + 1024;     // [128]
        float* red  = sm + 1152;     // [128]
        int ks = t >> 7, c = t & 127;
        int s0 = g_rowptr[0], s1 = g_rowptr[1];
        float acc = 0.f;
        for (int q = s0 + ks; q < s1; q += 8)
            acc += g_H3[(bid * N_ + g_col[q]) * C_ + c];
        part[ks * 128 + c] = acc;
        __syncthreads();
        if (t < 128) {
            float a = 0.f;
#pragma unroll
            for (int s = 0; s < 8; s++) a += part[s * 128 + t];
            s4[t] = a;
        }
        __syncthreads();
        int k0 = ks * 16;
        float p = 0.f;
#pragma unroll
        for (int k = k0; k < k0 + 16; k++) p += s4[k] * W_conv[k * C_ + c];
        __syncthreads();
        part[ks * 128 + c] = p;
        __syncthreads();
        if (t < 128) {
            float a2 = b_conv[t];
#pragma unroll
            for (int s = 0; s < 8; s++) a2 += part[s * 128 + t];
            red[t] = fmaxf(a2, 0.f) * W_cls[t];
        }
        __syncthreads();
#pragma unroll
        for (int off = 64; off > 0; off >>= 1) {
            if (t < off) red[t] += red[t + off];
            __syncthreads();
        }
        if (t == 0) out[bid] = red[0] + b_cls[0];
    } else if (bid == 64) {
        g_deg[t] = 0;
        if (t < 8) g_cnt[t] = 0;                  // reset DAG counters
    } else if (bid == 65) {
        g_flag2[t] = 0;
    } else if (bid == 66) {
        g_flag3[t] = 0;
    } else if (bid == 67) {
        int nd = g_nd;
        if (t < nd) g_flagd[(int)g_dval[t]] = 0;
        __syncthreads();
        if (t == 0) g_nd = 0;
    } else {
        // clear V count matrix (blocks 68..147): N_*VW ints
        for (int idx = (bid - 68) * NT + t; idx < N_ * VW; idx += 80 * NT)
            g_V[idx] = 0;
    }
}

extern "C" void kernel_launch(void* const* d_in, const int* in_sizes, int n_in,
                              void* d_out, int out_size) {
    (void)in_sizes; (void)n_in; (void)out_size;
    const float* x      = (const float*)d_in[0];
    const void*  eidx   = d_in[1];
    const float* W_emb  = (const float*)d_in[2];
    const float* b_emb  = (const float*)d_in[3];
    const float* W_conv = (const float*)d_in[4];
    const float* b_conv = (const float*)d_in[5];
    const float* W_cls  = (const float*)d_in[6];
    const float* b_cls  = (const float*)d_in[7];
    float* out = (float*)d_out;

    k_mega<<<NB, NT>>>(x, eidx, W_emb, b_emb, W_conv, b_conv, W_cls, b_cls, out);
}